// round 7
// baseline (speedup 1.0000x reference)
#include <cuda_runtime.h>
#include <cuda_bf16.h>

#define BB   16
#define CC   128
#define C2   256
#define OUTC 128
#define HH   128
#define WW   128
#define HW   16384
#define KGH  64
#define BGH  32
#define WKTOT   147456    /* OUT*C*9 */

typedef unsigned int u32;
typedef unsigned short u16;

// ---- scratch (device globals) ----
__device__ float g_pooled[BB * C2];
__device__ float g_hk[BB * KGH];
__device__ float g_hb[BB * BGH];
__device__ float g_dynb[BB * OUTC];
__device__ u32 g_ew2[OUTC * C2];                      // en_w split-packed (precomputed)
// packed bf16 split: low 16 bits = hi part, high 16 bits = lo part
__device__ u32 g_enh2[(size_t)BB * CC * HW];          // enhanced feature, split-packed
__device__ u32 g_wk2[(size_t)BB * 9 * CC * OUTC];     // dyn weights [b][tap][c][o], split-packed

__device__ __forceinline__ u32 pack_split(float v) {
    u16 hu = __bfloat16_as_ushort(__float2bfloat16(v));
    float rem = v - __bfloat162float(__ushort_as_bfloat16(hu));
    u16 lu = __bfloat16_as_ushort(__float2bfloat16(rem));
    return ((u32)lu << 16) | hu;
}

__device__ __forceinline__ void mma_bf16(float* d, u32 a0, u32 a1, u32 a2, u32 a3,
                                         u32 b0, u32 b1) {
    asm volatile(
        "mma.sync.aligned.m16n8k16.row.col.f32.bf16.bf16.f32 "
        "{%0,%1,%2,%3}, {%4,%5,%6,%7}, {%8,%9}, {%0,%1,%2,%3};"
        : "+f"(d[0]), "+f"(d[1]), "+f"(d[2]), "+f"(d[3])
        : "r"(a0), "r"(a1), "r"(a2), "r"(a3), "r"(b0), "r"(b1));
}

// ============================================================
// 1) global average pool of concat([ir, vi])
// ============================================================
__global__ void pool_kernel(const float* __restrict__ ir, const float* __restrict__ vi) {
    int bc = blockIdx.x;
    int b  = bc >> 8;
    int ch = bc & 255;
    const float* src = (ch < CC) ? ir + (size_t)(b * CC + ch) * HW
                                 : vi + (size_t)(b * CC + (ch - CC)) * HW;
    const float4* s4 = (const float4*)src;
    float sum = 0.f;
    for (int i = threadIdx.x; i < HW / 4; i += 256) {
        float4 v = s4[i];
        sum += v.x + v.y + v.z + v.w;
    }
    __shared__ float red[8];
    #pragma unroll
    for (int o = 16; o > 0; o >>= 1) sum += __shfl_down_sync(0xffffffffu, sum, o);
    if ((threadIdx.x & 31) == 0) red[threadIdx.x >> 5] = sum;
    __syncthreads();
    if (threadIdx.x == 0) {
        float t = 0.f;
        #pragma unroll
        for (int i = 0; i < 8; i++) t += red[i];
        g_pooled[b * C2 + ch] = t * (1.0f / HW);
    }
}

// ============================================================
// 2) hidden MLP layers
// ============================================================
__global__ void mlp1_kernel(const float* __restrict__ kg_w1, const float* __restrict__ kg_b1,
                            const float* __restrict__ bg_w1, const float* __restrict__ bg_b1) {
    int b = blockIdx.x;
    __shared__ float p[C2];
    for (int i = threadIdx.x; i < C2; i += 128) p[i] = g_pooled[b * C2 + i];
    __syncthreads();
    int t = threadIdx.x;
    if (t < KGH) {
        float acc = kg_b1[t];
        const float* w = kg_w1 + t * C2;
        for (int k = 0; k < C2; k++) acc = fmaf(p[k], w[k], acc);
        g_hk[b * KGH + t] = fmaxf(acc, 0.f);
    } else if (t < KGH + BGH) {
        int u = t - KGH;
        float acc = bg_b1[u];
        const float* w = bg_w1 + u * C2;
        for (int k = 0; k < C2; k++) acc = fmaf(p[k], w[k], acc);
        g_hb[b * BGH + u] = fmaxf(acc, 0.f);
    }
}

// ============================================================
// 3) dyn_k = hk @ kg_w2^T + kg_b2, written split-packed [b][t][c][o]
// ============================================================
__global__ void dynk_kernel(const float* __restrict__ kg_w2, const float* __restrict__ kg_b2) {
    int j = blockIdx.x * 256 + threadIdx.x;     // j = o*1152 + c*9 + t
    __shared__ float hk_s[BB * KGH];
    for (int i = threadIdx.x; i < BB * KGH; i += 256) hk_s[i] = g_hk[i];
    __syncthreads();
    float bias = kg_b2[j];
    float acc[BB];
    #pragma unroll
    for (int b = 0; b < BB; b++) acc[b] = bias;
    const float4* w4 = (const float4*)(kg_w2 + (size_t)j * KGH);
    for (int kk = 0; kk < KGH / 4; kk++) {
        float4 w = w4[kk];
        #pragma unroll
        for (int b = 0; b < BB; b++) {
            const float* h = hk_s + b * KGH + kk * 4;
            acc[b] += w.x * h[0] + w.y * h[1] + w.z * h[2] + w.w * h[3];
        }
    }
    int t = j % 9;
    int c = (j / 9) & 127;
    int o = j / 1152;
    #pragma unroll
    for (int b = 0; b < BB; b++)
        g_wk2[(((size_t)b * 9 + t) * CC + c) * OUTC + o] = pack_split(acc[b]);
}

// ============================================================
// 4) dyn_b
// ============================================================
__global__ void dynb_kernel(const float* __restrict__ bg_w2, const float* __restrict__ bg_b2) {
    int b = blockIdx.x, o = threadIdx.x;
    float acc = bg_b2[o];
    const float* w = bg_w2 + o * BGH;
    const float* h = g_hb + b * BGH;
    for (int k = 0; k < BGH; k++) acc = fmaf(w[k], h[k], acc);
    g_dynb[b * OUTC + o] = acc;
}

// ============================================================
// 4b) one-shot split of en_w
// ============================================================
__global__ void ewsplit_kernel(const float* __restrict__ en_w) {
    int i = blockIdx.x * 256 + threadIdx.x;     // 32768 elems
    g_ew2[i] = pack_split(en_w[i]);
}

// ============================================================
// 5) enhance GEMM on tensor cores (bf16 3-product split) + BN + ReLU
// ============================================================
__global__ __launch_bounds__(256) void enh_mma_kernel(
    const float* __restrict__ ir, const float* __restrict__ vi,
    const float* __restrict__ gmma, const float* __restrict__ beta,
    const float* __restrict__ mean, const float* __restrict__ var) {
    __shared__ u16 sWh[128 * 18];
    __shared__ u16 sWl[128 * 18];
    __shared__ u16 sXh[64 * 18];
    __shared__ u16 sXl[64 * 18];

    int b  = blockIdx.y;
    int p0 = blockIdx.x * 64;
    int tid  = threadIdx.x;
    int w    = tid >> 5;
    int lane = tid & 31;
    int g    = lane >> 2;
    int t2   = (lane & 3) * 2;

    float acc[8][4];
    #pragma unroll
    for (int i = 0; i < 8; i++)
        #pragma unroll
        for (int j = 0; j < 4; j++) acc[i][j] = 0.f;

    for (int k0 = 0; k0 < C2; k0 += 16) {
        // W chunk: 128 oc x 16 k (pre-split)
        #pragma unroll
        for (int r = 0; r < 8; r++) {
            int i = tid + r * 256;
            int oc = i >> 4, kk = i & 15;
            u32 v = g_ew2[oc * C2 + k0 + kk];
            sWh[oc * 18 + kk] = (u16)(v & 0xffffu);
            sWl[oc * 18 + kk] = (u16)(v >> 16);
        }
        // X chunk: 16 c x 64 px -> stored [px][k]
        #pragma unroll
        for (int r = 0; r < 4; r++) {
            int i = tid + r * 256;
            int cl = i >> 6, px = i & 63;
            int k = k0 + cl;
            const float* src = (k < CC) ? ir + (size_t)(b * CC + k) * HW
                                        : vi + (size_t)(b * CC + k - CC) * HW;
            u32 v = pack_split(src[p0 + px]);
            sXh[px * 18 + cl] = (u16)(v & 0xffffu);
            sXl[px * 18 + cl] = (u16)(v >> 16);
        }
        __syncthreads();

        int arow0 = (w * 16 + g) * 18;
        int arow1 = (w * 16 + g + 8) * 18;
        u32 ah0 = *(const u32*)(sWh + arow0 + t2);
        u32 ah1 = *(const u32*)(sWh + arow1 + t2);
        u32 ah2 = *(const u32*)(sWh + arow0 + t2 + 8);
        u32 ah3 = *(const u32*)(sWh + arow1 + t2 + 8);
        u32 al0 = *(const u32*)(sWl + arow0 + t2);
        u32 al1 = *(const u32*)(sWl + arow1 + t2);
        u32 al2 = *(const u32*)(sWl + arow0 + t2 + 8);
        u32 al3 = *(const u32*)(sWl + arow1 + t2 + 8);

        #pragma unroll
        for (int nf = 0; nf < 8; nf++) {
            int bidx = (nf * 8 + g) * 18 + t2;
            u32 bh0 = *(const u32*)(sXh + bidx);
            u32 bh1 = *(const u32*)(sXh + bidx + 8);
            u32 bl0 = *(const u32*)(sXl + bidx);
            u32 bl1 = *(const u32*)(sXl + bidx + 8);
            mma_bf16(acc[nf], ah0, ah1, ah2, ah3, bh0, bh1);
            mma_bf16(acc[nf], al0, al1, al2, al3, bh0, bh1);
            mma_bf16(acc[nf], ah0, ah1, ah2, ah3, bl0, bl1);
        }
        __syncthreads();
    }

    int oc0 = w * 16 + g;
    int oc1 = oc0 + 8;
    float inv0 = gmma[oc0] * rsqrtf(var[oc0] + 1e-5f);
    float sh0  = beta[oc0] - mean[oc0] * inv0;
    float inv1 = gmma[oc1] * rsqrtf(var[oc1] + 1e-5f);
    float sh1  = beta[oc1] - mean[oc1] * inv1;
    #pragma unroll
    for (int nf = 0; nf < 8; nf++) {
        int px = p0 + nf * 8 + t2;
        uint2 v0, v1;
        v0.x = pack_split(fmaxf(fmaf(acc[nf][0], inv0, sh0), 0.f));
        v0.y = pack_split(fmaxf(fmaf(acc[nf][1], inv0, sh0), 0.f));
        v1.x = pack_split(fmaxf(fmaf(acc[nf][2], inv1, sh1), 0.f));
        v1.y = pack_split(fmaxf(fmaf(acc[nf][3], inv1, sh1), 0.f));
        *(uint2*)&g_enh2[(size_t)(b * CC + oc0) * HW + px] = v0;
        *(uint2*)&g_enh2[(size_t)(b * CC + oc1) * HW + px] = v1;
    }
}

// ============================================================
// 6) dynamic conv: 9 tap-GEMMs on tensor cores, 8x16 px tile (R4 config)
// ============================================================
#define SW_HALF (9 * 64 * 18)     /* 10368 u16 */
#define SX_HALF (10 * 18 * 18)    /* 3240 u16  */
#define DSM_BYTES ((SW_HALF * 2 + SX_HALF * 2) * 2)

__global__ __launch_bounds__(256) void dconv_mma_kernel(float* __restrict__ out) {
    extern __shared__ u16 dsm[];
    u16* sWh = dsm;
    u16* sWl = sWh + SW_HALF;
    u16* sXh = sWl + SW_HALF;
    u16* sXl = sXh + SX_HALF;

    int b    = blockIdx.z;
    int oc0  = blockIdx.y * 64;
    int tile = blockIdx.x;                 // 16 row-bands x 8 col-tiles
    int r0  = (tile >> 3) * 8;
    int c0x = (tile & 7) * 16;

    int tid  = threadIdx.x;
    int w    = tid >> 5;
    int lane = tid & 31;
    int g    = lane >> 2;
    int t2   = (lane & 3) * 2;
    int f0   = (w & 3) * 2;
    int q0   = (w >> 2) * 4;

    float acc[2][4][4];
    #pragma unroll
    for (int i = 0; i < 2; i++)
        #pragma unroll
        for (int j = 0; j < 4; j++)
            #pragma unroll
            for (int k = 0; k < 4; k++) acc[i][j][k] = 0.f;

    for (int ch = 0; ch < 8; ch++) {
        for (int i = tid; i < 9 * 16 * 64; i += 256) {
            int o  = i & 63;
            int cl = (i >> 6) & 15;
            int t  = i >> 10;
            u32 v = g_wk2[(((size_t)b * 9 + t) * CC + ch * 16 + cl) * OUTC + oc0 + o];
            int si = (t * 64 + o) * 18 + cl;
            sWh[si] = (u16)(v & 0xffffu);
            sWl[si] = (u16)(v >> 16);
        }
        for (int i = tid; i < 2880; i += 256) {
            int col = i % 18;
            int row = (i / 18) % 10;
            int cl  = i / 180;
            int gr = r0 - 1 + row, gc = c0x - 1 + col;
            u32 v = 0;
            if ((unsigned)gr < 128u && (unsigned)gc < 128u)
                v = g_enh2[(((size_t)b * CC + ch * 16 + cl) << 14) + (gr << 7) + gc];
            int si = (row * 18 + col) * 18 + cl;
            sXh[si] = (u16)(v & 0xffffu);
            sXl[si] = (u16)(v >> 16);
        }
        __syncthreads();

        #pragma unroll
        for (int t = 0; t < 9; t++) {
            const int dr = t / 3, dc = t % 3;
            u32 bh[4][2], bl[4][2];
            #pragma unroll
            for (int qq = 0; qq < 4; qq++) {
                int widx = (t * 64 + (q0 + qq) * 8 + g) * 18 + t2;
                bh[qq][0] = *(const u32*)(sWh + widx);
                bh[qq][1] = *(const u32*)(sWh + widx + 8);
                bl[qq][0] = *(const u32*)(sWl + widx);
                bl[qq][1] = *(const u32*)(sWl + widx + 8);
            }
            #pragma unroll
            for (int ff = 0; ff < 2; ff++) {
                int f = f0 + ff;
                int p0i = ((f + dr) * 18 + g + dc) * 18 + t2;
                int p1i = ((f + dr) * 18 + g + 8 + dc) * 18 + t2;
                u32 ah0 = *(const u32*)(sXh + p0i);
                u32 ah1 = *(const u32*)(sXh + p1i);
                u32 ah2 = *(const u32*)(sXh + p0i + 8);
                u32 ah3 = *(const u32*)(sXh + p1i + 8);
                u32 al0 = *(const u32*)(sXl + p0i);
                u32 al1 = *(const u32*)(sXl + p1i);
                u32 al2 = *(const u32*)(sXl + p0i + 8);
                u32 al3 = *(const u32*)(sXl + p1i + 8);
                #pragma unroll
                for (int qq = 0; qq < 4; qq++) {
                    mma_bf16(acc[ff][qq], ah0, ah1, ah2, ah3, bh[qq][0], bh[qq][1]);
                    mma_bf16(acc[ff][qq], al0, al1, al2, al3, bh[qq][0], bh[qq][1]);
                    mma_bf16(acc[ff][qq], ah0, ah1, ah2, ah3, bl[qq][0], bl[qq][1]);
                }
            }
        }
        __syncthreads();
    }

    #pragma unroll
    for (int ff = 0; ff < 2; ff++) {
        int orow = r0 + f0 + ff;
        #pragma unroll
        for (int qq = 0; qq < 4; qq++) {
            int oca = oc0 + (q0 + qq) * 8 + t2;
            float ba = g_dynb[b * OUTC + oca];
            float bb = g_dynb[b * OUTC + oca + 1];
            size_t basea = ((size_t)(b * OUTC + oca) * HH + orow) * WW + c0x + g;
            size_t baseb = ((size_t)(b * OUTC + oca + 1) * HH + orow) * WW + c0x + g;
            out[basea]     = acc[ff][qq][0] + ba;
            out[baseb]     = acc[ff][qq][1] + bb;
            out[basea + 8] = acc[ff][qq][2] + ba;
            out[baseb + 8] = acc[ff][qq][3] + bb;
        }
    }
}

// ============================================================
extern "C" void kernel_launch(void* const* d_in, const int* in_sizes, int n_in,
                              void* d_out, int out_size) {
    const float* ir    = (const float*)d_in[0];
    const float* vi    = (const float*)d_in[1];
    const float* kg_w1 = (const float*)d_in[2];
    const float* kg_b1 = (const float*)d_in[3];
    const float* kg_w2 = (const float*)d_in[4];
    const float* kg_b2 = (const float*)d_in[5];
    const float* bg_w1 = (const float*)d_in[6];
    const float* bg_b1 = (const float*)d_in[7];
    const float* bg_w2 = (const float*)d_in[8];
    const float* bg_b2 = (const float*)d_in[9];
    const float* en_w  = (const float*)d_in[10];
    const float* gmma  = (const float*)d_in[11];
    const float* beta  = (const float*)d_in[12];
    const float* mean  = (const float*)d_in[13];
    const float* var   = (const float*)d_in[14];
    float* out = (float*)d_out;

    static cudaStream_t s2 = nullptr;
    static cudaEvent_t evFork = nullptr, evJoin = nullptr;
    if (!s2) {
        cudaStreamCreateWithFlags(&s2, cudaStreamNonBlocking);
        cudaEventCreateWithFlags(&evFork, cudaEventDisableTiming);
        cudaEventCreateWithFlags(&evJoin, cudaEventDisableTiming);
        cudaFuncSetAttribute(dconv_mma_kernel,
                             cudaFuncAttributeMaxDynamicSharedMemorySize, DSM_BYTES);
    }

    // fork: branch B (en_w split -> enhance) on s2
    cudaEventRecord(evFork, 0);
    cudaStreamWaitEvent(s2, evFork, 0);
    ewsplit_kernel<<<OUTC * C2 / 256, 256, 0, s2>>>(en_w);
    enh_mma_kernel<<<dim3(HW / 64, BB), 256, 0, s2>>>(ir, vi, gmma, beta, mean, var);

    // branch A (pool -> mlps -> dyn weights) on default stream
    pool_kernel<<<BB * C2, 256>>>(ir, vi);
    mlp1_kernel<<<BB, 128>>>(kg_w1, kg_b1, bg_w1, bg_b1);
    dynk_kernel<<<WKTOT / 256, 256>>>(kg_w2, kg_b2);
    dynb_kernel<<<BB, OUTC>>>(bg_w2, bg_b2);

    // join: dconv needs both branches
    cudaEventRecord(evJoin, s2);
    cudaStreamWaitEvent(0, evJoin, 0);
    dconv_mma_kernel<<<dim3(128, 2, BB), 256, DSM_BYTES>>>(out);
}

// round 8
// speedup vs baseline: 1.4638x; 1.4638x over previous
#include <cuda_runtime.h>
#include <cuda_bf16.h>

#define BB   16
#define CC   128
#define C2   256
#define OUTC 128
#define HH   128
#define WW   128
#define HW   16384
#define KGH  64
#define BGH  32
#define WKTOT   147456    /* OUT*C*9 */

typedef unsigned int u32;
typedef unsigned short u16;

// ---- scratch (device globals) ----
__device__ float g_pooled[BB * C2];
__device__ float g_hk[BB * KGH];
__device__ float g_hb[BB * BGH];
__device__ float g_dynb[BB * OUTC];
__device__ u32 g_ew2[OUTC * C2];                      // en_w split-packed (precomputed)
// packed bf16 split: low 16 bits = hi part, high 16 bits = lo part
__device__ u32 g_enh2[(size_t)BB * CC * HW];          // enhanced feature, split-packed
__device__ u32 g_wk2[(size_t)BB * 9 * CC * OUTC];     // dyn weights [b][tap][c][o], split-packed

__device__ __forceinline__ u32 pack_split(float v) {
    u16 hu = __bfloat16_as_ushort(__float2bfloat16(v));
    float rem = v - __bfloat162float(__ushort_as_bfloat16(hu));
    u16 lu = __bfloat16_as_ushort(__float2bfloat16(rem));
    return ((u32)lu << 16) | hu;
}

__device__ __forceinline__ void mma_bf16(float* d, u32 a0, u32 a1, u32 a2, u32 a3,
                                         u32 b0, u32 b1) {
    asm volatile(
        "mma.sync.aligned.m16n8k16.row.col.f32.bf16.bf16.f32 "
        "{%0,%1,%2,%3}, {%4,%5,%6,%7}, {%8,%9}, {%0,%1,%2,%3};"
        : "+f"(d[0]), "+f"(d[1]), "+f"(d[2]), "+f"(d[3])
        : "r"(a0), "r"(a1), "r"(a2), "r"(a3), "r"(b0), "r"(b1));
}

// ============================================================
// 1) global average pool of concat([ir, vi])
// ============================================================
__global__ void pool_kernel(const float* __restrict__ ir, const float* __restrict__ vi) {
    int bc = blockIdx.x;
    int b  = bc >> 8;
    int ch = bc & 255;
    const float* src = (ch < CC) ? ir + (size_t)(b * CC + ch) * HW
                                 : vi + (size_t)(b * CC + (ch - CC)) * HW;
    const float4* s4 = (const float4*)src;
    float sum = 0.f;
    for (int i = threadIdx.x; i < HW / 4; i += 256) {
        float4 v = s4[i];
        sum += v.x + v.y + v.z + v.w;
    }
    __shared__ float red[8];
    #pragma unroll
    for (int o = 16; o > 0; o >>= 1) sum += __shfl_down_sync(0xffffffffu, sum, o);
    if ((threadIdx.x & 31) == 0) red[threadIdx.x >> 5] = sum;
    __syncthreads();
    if (threadIdx.x == 0) {
        float t = 0.f;
        #pragma unroll
        for (int i = 0; i < 8; i++) t += red[i];
        g_pooled[b * C2 + ch] = t * (1.0f / HW);
    }
}

// ============================================================
// 2) hidden MLP layers
// ============================================================
__global__ void mlp1_kernel(const float* __restrict__ kg_w1, const float* __restrict__ kg_b1,
                            const float* __restrict__ bg_w1, const float* __restrict__ bg_b1) {
    int b = blockIdx.x;
    __shared__ float p[C2];
    for (int i = threadIdx.x; i < C2; i += 128) p[i] = g_pooled[b * C2 + i];
    __syncthreads();
    int t = threadIdx.x;
    if (t < KGH) {
        float acc = kg_b1[t];
        const float* w = kg_w1 + t * C2;
        for (int k = 0; k < C2; k++) acc = fmaf(p[k], w[k], acc);
        g_hk[b * KGH + t] = fmaxf(acc, 0.f);
    } else if (t < KGH + BGH) {
        int u = t - KGH;
        float acc = bg_b1[u];
        const float* w = bg_w1 + u * C2;
        for (int k = 0; k < C2; k++) acc = fmaf(p[k], w[k], acc);
        g_hb[b * BGH + u] = fmaxf(acc, 0.f);
    }
}

// ============================================================
// 3) dyn_k = hk @ kg_w2^T + kg_b2, written split-packed [b][t][c][o]
// ============================================================
__global__ void dynk_kernel(const float* __restrict__ kg_w2, const float* __restrict__ kg_b2) {
    int j = blockIdx.x * 256 + threadIdx.x;     // j = o*1152 + c*9 + t
    __shared__ float hk_s[BB * KGH];
    for (int i = threadIdx.x; i < BB * KGH; i += 256) hk_s[i] = g_hk[i];
    __syncthreads();
    float bias = kg_b2[j];
    float acc[BB];
    #pragma unroll
    for (int b = 0; b < BB; b++) acc[b] = bias;
    const float4* w4 = (const float4*)(kg_w2 + (size_t)j * KGH);
    for (int kk = 0; kk < KGH / 4; kk++) {
        float4 w = w4[kk];
        #pragma unroll
        for (int b = 0; b < BB; b++) {
            const float* h = hk_s + b * KGH + kk * 4;
            acc[b] += w.x * h[0] + w.y * h[1] + w.z * h[2] + w.w * h[3];
        }
    }
    int t = j % 9;
    int c = (j / 9) & 127;
    int o = j / 1152;
    #pragma unroll
    for (int b = 0; b < BB; b++)
        g_wk2[(((size_t)b * 9 + t) * CC + c) * OUTC + o] = pack_split(acc[b]);
}

// ============================================================
// 4) dyn_b
// ============================================================
__global__ void dynb_kernel(const float* __restrict__ bg_w2, const float* __restrict__ bg_b2) {
    int b = blockIdx.x, o = threadIdx.x;
    float acc = bg_b2[o];
    const float* w = bg_w2 + o * BGH;
    const float* h = g_hb + b * BGH;
    for (int k = 0; k < BGH; k++) acc = fmaf(w[k], h[k], acc);
    g_dynb[b * OUTC + o] = acc;
}

// ============================================================
// 4b) one-shot split of en_w
// ============================================================
__global__ void ewsplit_kernel(const float* __restrict__ en_w) {
    int i = blockIdx.x * 256 + threadIdx.x;     // 32768 elems
    g_ew2[i] = pack_split(en_w[i]);
}

// ============================================================
// 5) enhance GEMM on tensor cores (bf16 3-product split) + BN + ReLU
// ============================================================
__global__ __launch_bounds__(256) void enh_mma_kernel(
    const float* __restrict__ ir, const float* __restrict__ vi,
    const float* __restrict__ gmma, const float* __restrict__ beta,
    const float* __restrict__ mean, const float* __restrict__ var) {
    __shared__ u16 sWh[128 * 18];
    __shared__ u16 sWl[128 * 18];
    __shared__ u16 sXh[64 * 18];
    __shared__ u16 sXl[64 * 18];

    int b  = blockIdx.y;
    int p0 = blockIdx.x * 64;
    int tid  = threadIdx.x;
    int w    = tid >> 5;
    int lane = tid & 31;
    int g    = lane >> 2;
    int t2   = (lane & 3) * 2;

    float acc[8][4];
    #pragma unroll
    for (int i = 0; i < 8; i++)
        #pragma unroll
        for (int j = 0; j < 4; j++) acc[i][j] = 0.f;

    for (int k0 = 0; k0 < C2; k0 += 16) {
        // W chunk: 128 oc x 16 k (pre-split)
        #pragma unroll
        for (int r = 0; r < 8; r++) {
            int i = tid + r * 256;
            int oc = i >> 4, kk = i & 15;
            u32 v = g_ew2[oc * C2 + k0 + kk];
            sWh[oc * 18 + kk] = (u16)(v & 0xffffu);
            sWl[oc * 18 + kk] = (u16)(v >> 16);
        }
        // X chunk: 16 c x 64 px -> stored [px][k]
        #pragma unroll
        for (int r = 0; r < 4; r++) {
            int i = tid + r * 256;
            int cl = i >> 6, px = i & 63;
            int k = k0 + cl;
            const float* src = (k < CC) ? ir + (size_t)(b * CC + k) * HW
                                        : vi + (size_t)(b * CC + k - CC) * HW;
            u32 v = pack_split(src[p0 + px]);
            sXh[px * 18 + cl] = (u16)(v & 0xffffu);
            sXl[px * 18 + cl] = (u16)(v >> 16);
        }
        __syncthreads();

        int arow0 = (w * 16 + g) * 18;
        int arow1 = (w * 16 + g + 8) * 18;
        u32 ah0 = *(const u32*)(sWh + arow0 + t2);
        u32 ah1 = *(const u32*)(sWh + arow1 + t2);
        u32 ah2 = *(const u32*)(sWh + arow0 + t2 + 8);
        u32 ah3 = *(const u32*)(sWh + arow1 + t2 + 8);
        u32 al0 = *(const u32*)(sWl + arow0 + t2);
        u32 al1 = *(const u32*)(sWl + arow1 + t2);
        u32 al2 = *(const u32*)(sWl + arow0 + t2 + 8);
        u32 al3 = *(const u32*)(sWl + arow1 + t2 + 8);

        #pragma unroll
        for (int nf = 0; nf < 8; nf++) {
            int bidx = (nf * 8 + g) * 18 + t2;
            u32 bh0 = *(const u32*)(sXh + bidx);
            u32 bh1 = *(const u32*)(sXh + bidx + 8);
            u32 bl0 = *(const u32*)(sXl + bidx);
            u32 bl1 = *(const u32*)(sXl + bidx + 8);
            mma_bf16(acc[nf], ah0, ah1, ah2, ah3, bh0, bh1);
            mma_bf16(acc[nf], al0, al1, al2, al3, bh0, bh1);
            mma_bf16(acc[nf], ah0, ah1, ah2, ah3, bl0, bl1);
        }
        __syncthreads();
    }

    int oc0 = w * 16 + g;
    int oc1 = oc0 + 8;
    float inv0 = gmma[oc0] * rsqrtf(var[oc0] + 1e-5f);
    float sh0  = beta[oc0] - mean[oc0] * inv0;
    float inv1 = gmma[oc1] * rsqrtf(var[oc1] + 1e-5f);
    float sh1  = beta[oc1] - mean[oc1] * inv1;
    #pragma unroll
    for (int nf = 0; nf < 8; nf++) {
        int px = p0 + nf * 8 + t2;
        uint2 v0, v1;
        v0.x = pack_split(fmaxf(fmaf(acc[nf][0], inv0, sh0), 0.f));
        v0.y = pack_split(fmaxf(fmaf(acc[nf][1], inv0, sh0), 0.f));
        v1.x = pack_split(fmaxf(fmaf(acc[nf][2], inv1, sh1), 0.f));
        v1.y = pack_split(fmaxf(fmaf(acc[nf][3], inv1, sh1), 0.f));
        *(uint2*)&g_enh2[(size_t)(b * CC + oc0) * HW + px] = v0;
        *(uint2*)&g_enh2[(size_t)(b * CC + oc1) * HW + px] = v1;
    }
}

// ============================================================
// 6) dynamic conv: 9 tap-GEMMs on tensor cores, 8x16 px tile (R4 config)
// ============================================================
#define SW_HALF (9 * 64 * 18)     /* 10368 u16 */
#define SX_HALF (10 * 18 * 18)    /* 3240 u16  */
#define DSM_BYTES ((SW_HALF * 2 + SX_HALF * 2) * 2)

__global__ __launch_bounds__(256) void dconv_mma_kernel(float* __restrict__ out) {
    extern __shared__ u16 dsm[];
    u16* sWh = dsm;
    u16* sWl = sWh + SW_HALF;
    u16* sXh = sWl + SW_HALF;
    u16* sXl = sXh + SX_HALF;

    int b    = blockIdx.z;
    int oc0  = blockIdx.y * 64;
    int tile = blockIdx.x;                 // 16 row-bands x 8 col-tiles
    int r0  = (tile >> 3) * 8;
    int c0x = (tile & 7) * 16;

    int tid  = threadIdx.x;
    int w    = tid >> 5;
    int lane = tid & 31;
    int g    = lane >> 2;
    int t2   = (lane & 3) * 2;
    int f0   = (w & 3) * 2;
    int q0   = (w >> 2) * 4;

    float acc[2][4][4];
    #pragma unroll
    for (int i = 0; i < 2; i++)
        #pragma unroll
        for (int j = 0; j < 4; j++)
            #pragma unroll
            for (int k = 0; k < 4; k++) acc[i][j][k] = 0.f;

    for (int ch = 0; ch < 8; ch++) {
        for (int i = tid; i < 9 * 16 * 64; i += 256) {
            int o  = i & 63;
            int cl = (i >> 6) & 15;
            int t  = i >> 10;
            u32 v = g_wk2[(((size_t)b * 9 + t) * CC + ch * 16 + cl) * OUTC + oc0 + o];
            int si = (t * 64 + o) * 18 + cl;
            sWh[si] = (u16)(v & 0xffffu);
            sWl[si] = (u16)(v >> 16);
        }
        for (int i = tid; i < 2880; i += 256) {
            int col = i % 18;
            int row = (i / 18) % 10;
            int cl  = i / 180;
            int gr = r0 - 1 + row, gc = c0x - 1 + col;
            u32 v = 0;
            if ((unsigned)gr < 128u && (unsigned)gc < 128u)
                v = g_enh2[(((size_t)b * CC + ch * 16 + cl) << 14) + (gr << 7) + gc];
            int si = (row * 18 + col) * 18 + cl;
            sXh[si] = (u16)(v & 0xffffu);
            sXl[si] = (u16)(v >> 16);
        }
        __syncthreads();

        #pragma unroll
        for (int t = 0; t < 9; t++) {
            const int dr = t / 3, dc = t % 3;
            u32 bh[4][2], bl[4][2];
            #pragma unroll
            for (int qq = 0; qq < 4; qq++) {
                int widx = (t * 64 + (q0 + qq) * 8 + g) * 18 + t2;
                bh[qq][0] = *(const u32*)(sWh + widx);
                bh[qq][1] = *(const u32*)(sWh + widx + 8);
                bl[qq][0] = *(const u32*)(sWl + widx);
                bl[qq][1] = *(const u32*)(sWl + widx + 8);
            }
            #pragma unroll
            for (int ff = 0; ff < 2; ff++) {
                int f = f0 + ff;
                int p0i = ((f + dr) * 18 + g + dc) * 18 + t2;
                int p1i = ((f + dr) * 18 + g + 8 + dc) * 18 + t2;
                u32 ah0 = *(const u32*)(sXh + p0i);
                u32 ah1 = *(const u32*)(sXh + p1i);
                u32 ah2 = *(const u32*)(sXh + p0i + 8);
                u32 ah3 = *(const u32*)(sXh + p1i + 8);
                u32 al0 = *(const u32*)(sXl + p0i);
                u32 al1 = *(const u32*)(sXl + p1i);
                u32 al2 = *(const u32*)(sXl + p0i + 8);
                u32 al3 = *(const u32*)(sXl + p1i + 8);
                #pragma unroll
                for (int qq = 0; qq < 4; qq++) {
                    mma_bf16(acc[ff][qq], ah0, ah1, ah2, ah3, bh[qq][0], bh[qq][1]);
                    mma_bf16(acc[ff][qq], al0, al1, al2, al3, bh[qq][0], bh[qq][1]);
                    mma_bf16(acc[ff][qq], ah0, ah1, ah2, ah3, bl[qq][0], bl[qq][1]);
                }
            }
        }
        __syncthreads();
    }

    #pragma unroll
    for (int ff = 0; ff < 2; ff++) {
        int orow = r0 + f0 + ff;
        #pragma unroll
        for (int qq = 0; qq < 4; qq++) {
            int oca = oc0 + (q0 + qq) * 8 + t2;
            float ba = g_dynb[b * OUTC + oca];
            float bb = g_dynb[b * OUTC + oca + 1];
            size_t basea = ((size_t)(b * OUTC + oca) * HH + orow) * WW + c0x + g;
            size_t baseb = ((size_t)(b * OUTC + oca + 1) * HH + orow) * WW + c0x + g;
            out[basea]     = acc[ff][qq][0] + ba;
            out[baseb]     = acc[ff][qq][1] + bb;
            out[basea + 8] = acc[ff][qq][2] + ba;
            out[baseb + 8] = acc[ff][qq][3] + bb;
        }
    }
}

// ============================================================
extern "C" void kernel_launch(void* const* d_in, const int* in_sizes, int n_in,
                              void* d_out, int out_size) {
    const float* ir    = (const float*)d_in[0];
    const float* vi    = (const float*)d_in[1];
    const float* kg_w1 = (const float*)d_in[2];
    const float* kg_b1 = (const float*)d_in[3];
    const float* kg_w2 = (const float*)d_in[4];
    const float* kg_b2 = (const float*)d_in[5];
    const float* bg_w1 = (const float*)d_in[6];
    const float* bg_b1 = (const float*)d_in[7];
    const float* bg_w2 = (const float*)d_in[8];
    const float* bg_b2 = (const float*)d_in[9];
    const float* en_w  = (const float*)d_in[10];
    const float* gmma  = (const float*)d_in[11];
    const float* beta  = (const float*)d_in[12];
    const float* mean  = (const float*)d_in[13];
    const float* var   = (const float*)d_in[14];
    float* out = (float*)d_out;

    static int smem_set = 0;
    if (!smem_set) {
        cudaFuncSetAttribute(dconv_mma_kernel,
                             cudaFuncAttributeMaxDynamicSharedMemorySize, DSM_BYTES);
        smem_set = 1;
    }

    pool_kernel<<<BB * C2, 256>>>(ir, vi);
    mlp1_kernel<<<BB, 128>>>(kg_w1, kg_b1, bg_w1, bg_b1);
    dynk_kernel<<<WKTOT / 256, 256>>>(kg_w2, kg_b2);
    dynb_kernel<<<BB, OUTC>>>(bg_w2, bg_b2);
    ewsplit_kernel<<<OUTC * C2 / 256, 256>>>(en_w);
    enh_mma_kernel<<<dim3(HW / 64, BB), 256>>>(ir, vi, gmma, beta, mean, var);
    dconv_mma_kernel<<<dim3(128, 2, BB), 256, DSM_BYTES>>>(out);
}

// round 10
// speedup vs baseline: 1.6799x; 1.1477x over previous
#include <cuda_runtime.h>
#include <cuda_fp16.h>

#define BB   16
#define CC   128
#define C2   256
#define OUTC 128
#define HH   128
#define WW   128
#define HW   16384
#define KGH  64
#define BGH  32
#define WKTOT   147456    /* OUT*C*9 */

typedef unsigned int u32;
typedef unsigned short u16;

// ---- scratch (device globals) ----
__device__ float g_pooled[BB * C2];
__device__ float g_hk[BB * KGH];
__device__ float g_hb[BB * BGH];
__device__ float g_dynb[BB * OUTC];
__device__ u32 g_ew2[OUTC * C2];                      // en_w fp16 split-packed
// packed fp16 split: low 16 bits = hi part, high 16 bits = lo (residual) part
__device__ u32 g_enh2[(size_t)BB * CC * HW];          // enhanced feature, split-packed
__device__ u32 g_wk2[(size_t)BB * 9 * CC * OUTC];     // dyn weights [b][tap][c][o], split-packed

// fp16 two-term split: v = hi + lo (exact to ~2^-22)
__device__ __forceinline__ u32 pack_split(float v) {
    __half h = __float2half(v);
    u16 hu = __half_as_ushort(h);
    float rem = v - __half2float(h);
    u16 lu = __half_as_ushort(__float2half(rem));
    return ((u32)lu << 16) | hu;
}

__device__ __forceinline__ void mma_f16(float* d, u32 a0, u32 a1, u32 a2, u32 a3,
                                        u32 b0, u32 b1) {
    asm volatile(
        "mma.sync.aligned.m16n8k16.row.col.f32.f16.f16.f32 "
        "{%0,%1,%2,%3}, {%4,%5,%6,%7}, {%8,%9}, {%0,%1,%2,%3};"
        : "+f"(d[0]), "+f"(d[1]), "+f"(d[2]), "+f"(d[3])
        : "r"(a0), "r"(a1), "r"(a2), "r"(a3), "r"(b0), "r"(b1));
}

// ============================================================
// 1) global average pool of concat([ir, vi])
// ============================================================
__global__ void pool_kernel(const float* __restrict__ ir, const float* __restrict__ vi) {
    int bc = blockIdx.x;
    int b  = bc >> 8;
    int ch = bc & 255;
    const float* src = (ch < CC) ? ir + (size_t)(b * CC + ch) * HW
                                 : vi + (size_t)(b * CC + (ch - CC)) * HW;
    const float4* s4 = (const float4*)src;
    float sum = 0.f;
    for (int i = threadIdx.x; i < HW / 4; i += 256) {
        float4 v = s4[i];
        sum += v.x + v.y + v.z + v.w;
    }
    __shared__ float red[8];
    #pragma unroll
    for (int o = 16; o > 0; o >>= 1) sum += __shfl_down_sync(0xffffffffu, sum, o);
    if ((threadIdx.x & 31) == 0) red[threadIdx.x >> 5] = sum;
    __syncthreads();
    if (threadIdx.x == 0) {
        float t = 0.f;
        #pragma unroll
        for (int i = 0; i < 8; i++) t += red[i];
        g_pooled[b * C2 + ch] = t * (1.0f / HW);
    }
}

// ============================================================
// 2) hidden MLP layers
// ============================================================
__global__ void mlp1_kernel(const float* __restrict__ kg_w1, const float* __restrict__ kg_b1,
                            const float* __restrict__ bg_w1, const float* __restrict__ bg_b1) {
    int b = blockIdx.x;
    __shared__ float p[C2];
    for (int i = threadIdx.x; i < C2; i += 128) p[i] = g_pooled[b * C2 + i];
    __syncthreads();
    int t = threadIdx.x;
    if (t < KGH) {
        float acc = kg_b1[t];
        const float* w = kg_w1 + t * C2;
        for (int k = 0; k < C2; k++) acc = fmaf(p[k], w[k], acc);
        g_hk[b * KGH + t] = fmaxf(acc, 0.f);
    } else if (t < KGH + BGH) {
        int u = t - KGH;
        float acc = bg_b1[u];
        const float* w = bg_w1 + u * C2;
        for (int k = 0; k < C2; k++) acc = fmaf(p[k], w[k], acc);
        g_hb[b * BGH + u] = fmaxf(acc, 0.f);
    }
}

// ============================================================
// 3) dyn_k = hk @ kg_w2^T + kg_b2, written split-packed [b][t][c][o]
// ============================================================
__global__ void dynk_kernel(const float* __restrict__ kg_w2, const float* __restrict__ kg_b2) {
    int j = blockIdx.x * 256 + threadIdx.x;     // j = o*1152 + c*9 + t
    __shared__ float hk_s[BB * KGH];
    for (int i = threadIdx.x; i < BB * KGH; i += 256) hk_s[i] = g_hk[i];
    __syncthreads();
    float bias = kg_b2[j];
    float acc[BB];
    #pragma unroll
    for (int b = 0; b < BB; b++) acc[b] = bias;
    const float4* w4 = (const float4*)(kg_w2 + (size_t)j * KGH);
    for (int kk = 0; kk < KGH / 4; kk++) {
        float4 w = w4[kk];
        #pragma unroll
        for (int b = 0; b < BB; b++) {
            const float* h = hk_s + b * KGH + kk * 4;
            acc[b] += w.x * h[0] + w.y * h[1] + w.z * h[2] + w.w * h[3];
        }
    }
    int t = j % 9;
    int c = (j / 9) & 127;
    int o = j / 1152;
    #pragma unroll
    for (int b = 0; b < BB; b++)
        g_wk2[(((size_t)b * 9 + t) * CC + c) * OUTC + o] = pack_split(acc[b]);
}

// ============================================================
// 4) dyn_b
// ============================================================
__global__ void dynb_kernel(const float* __restrict__ bg_w2, const float* __restrict__ bg_b2) {
    int b = blockIdx.x, o = threadIdx.x;
    float acc = bg_b2[o];
    const float* w = bg_w2 + o * BGH;
    const float* h = g_hb + b * BGH;
    for (int k = 0; k < BGH; k++) acc = fmaf(w[k], h[k], acc);
    g_dynb[b * OUTC + o] = acc;
}

// ============================================================
// 4b) one-shot fp16 split of en_w
// ============================================================
__global__ void ewsplit_kernel(const float* __restrict__ en_w) {
    int i = blockIdx.x * 256 + threadIdx.x;     // 32768 elems
    g_ew2[i] = pack_split(en_w[i]);
}

// ============================================================
// 5) enhance GEMM on tensor cores (fp16 2-product) + BN + ReLU
//    A = en_w split (Wh+Wl exact), B = X rounded to single fp16
//    error = W * eps(X) ~ 2^-12 relative, random sign
// ============================================================
__global__ __launch_bounds__(256) void enh_mma_kernel(
    const float* __restrict__ ir, const float* __restrict__ vi,
    const float* __restrict__ gmma, const float* __restrict__ beta,
    const float* __restrict__ mean, const float* __restrict__ var) {
    __shared__ u16 sWh[128 * 18];
    __shared__ u16 sWl[128 * 18];
    __shared__ u16 sXh[64 * 18];

    int b  = blockIdx.y;
    int p0 = blockIdx.x * 64;
    int tid  = threadIdx.x;
    int w    = tid >> 5;
    int lane = tid & 31;
    int g    = lane >> 2;
    int t2   = (lane & 3) * 2;

    float acc[8][4];
    #pragma unroll
    for (int i = 0; i < 8; i++)
        #pragma unroll
        for (int j = 0; j < 4; j++) acc[i][j] = 0.f;

    for (int k0 = 0; k0 < C2; k0 += 16) {
        // W chunk: 128 oc x 16 k (pre-split fp16 hi/lo)
        #pragma unroll
        for (int r = 0; r < 8; r++) {
            int i = tid + r * 256;
            int oc = i >> 4, kk = i & 15;
            u32 v = g_ew2[oc * C2 + k0 + kk];
            sWh[oc * 18 + kk] = (u16)(v & 0xffffu);
            sWl[oc * 18 + kk] = (u16)(v >> 16);
        }
        // X chunk: 16 c x 64 px -> stored [px][k], single fp16
        #pragma unroll
        for (int r = 0; r < 4; r++) {
            int i = tid + r * 256;
            int cl = i >> 6, px = i & 63;
            int k = k0 + cl;
            const float* src = (k < CC) ? ir + (size_t)(b * CC + k) * HW
                                        : vi + (size_t)(b * CC + k - CC) * HW;
            sXh[px * 18 + cl] = __half_as_ushort(__float2half(src[p0 + px]));
        }
        __syncthreads();

        int arow0 = (w * 16 + g) * 18;
        int arow1 = (w * 16 + g + 8) * 18;
        u32 ah0 = *(const u32*)(sWh + arow0 + t2);
        u32 ah1 = *(const u32*)(sWh + arow1 + t2);
        u32 ah2 = *(const u32*)(sWh + arow0 + t2 + 8);
        u32 ah3 = *(const u32*)(sWh + arow1 + t2 + 8);
        u32 al0 = *(const u32*)(sWl + arow0 + t2);
        u32 al1 = *(const u32*)(sWl + arow1 + t2);
        u32 al2 = *(const u32*)(sWl + arow0 + t2 + 8);
        u32 al3 = *(const u32*)(sWl + arow1 + t2 + 8);

        #pragma unroll
        for (int nf = 0; nf < 8; nf++) {
            int bidx = (nf * 8 + g) * 18 + t2;
            u32 bh0 = *(const u32*)(sXh + bidx);
            u32 bh1 = *(const u32*)(sXh + bidx + 8);
            mma_f16(acc[nf], ah0, ah1, ah2, ah3, bh0, bh1);
            mma_f16(acc[nf], al0, al1, al2, al3, bh0, bh1);
        }
        __syncthreads();
    }

    int oc0 = w * 16 + g;
    int oc1 = oc0 + 8;
    float inv0 = gmma[oc0] * rsqrtf(var[oc0] + 1e-5f);
    float sh0  = beta[oc0] - mean[oc0] * inv0;
    float inv1 = gmma[oc1] * rsqrtf(var[oc1] + 1e-5f);
    float sh1  = beta[oc1] - mean[oc1] * inv1;
    #pragma unroll
    for (int nf = 0; nf < 8; nf++) {
        int px = p0 + nf * 8 + t2;
        uint2 v0, v1;
        v0.x = pack_split(fmaxf(fmaf(acc[nf][0], inv0, sh0), 0.f));
        v0.y = pack_split(fmaxf(fmaf(acc[nf][1], inv0, sh0), 0.f));
        v1.x = pack_split(fmaxf(fmaf(acc[nf][2], inv1, sh1), 0.f));
        v1.y = pack_split(fmaxf(fmaf(acc[nf][3], inv1, sh1), 0.f));
        *(uint2*)&g_enh2[(size_t)(b * CC + oc0) * HW + px] = v0;
        *(uint2*)&g_enh2[(size_t)(b * CC + oc1) * HW + px] = v1;
    }
}

// ============================================================
// 6) dynamic conv: 9 tap-GEMMs, fp16 2-product, 8x16 px tile
//    A = X split (Xh+Xl exact), B = W rounded to single fp16
//    error = X * eps(W) ~ 2^-12 relative, random sign
// ============================================================
#define SW_HALF (9 * 64 * 18)     /* 10368 u16 (hi plane only) */
#define SX_HALF (10 * 18 * 18)    /* 3240 u16  */
#define DSM_BYTES ((SW_HALF + SX_HALF * 2) * 2)

__global__ __launch_bounds__(256) void dconv_mma_kernel(float* __restrict__ out) {
    extern __shared__ u16 dsm[];
    u16* sWh = dsm;
    u16* sXh = sWh + SW_HALF;
    u16* sXl = sXh + SX_HALF;

    int b    = blockIdx.z;
    int oc0  = blockIdx.y * 64;
    int tile = blockIdx.x;                 // 16 row-bands x 8 col-tiles
    int r0  = (tile >> 3) * 8;
    int c0x = (tile & 7) * 16;

    int tid  = threadIdx.x;
    int w    = tid >> 5;
    int lane = tid & 31;
    int g    = lane >> 2;
    int t2   = (lane & 3) * 2;
    int f0   = (w & 3) * 2;
    int q0   = (w >> 2) * 4;

    float acc[2][4][4];
    #pragma unroll
    for (int i = 0; i < 2; i++)
        #pragma unroll
        for (int j = 0; j < 4; j++)
            #pragma unroll
            for (int k = 0; k < 4; k++) acc[i][j][k] = 0.f;

    for (int ch = 0; ch < 8; ch++) {
        // W chunk (hi plane only): [tap][o(64)][c(16 pad 18)]
        for (int i = tid; i < 9 * 16 * 64; i += 256) {
            int o  = i & 63;
            int cl = (i >> 6) & 15;
            int t  = i >> 10;
            u32 v = g_wk2[(((size_t)b * 9 + t) * CC + ch * 16 + cl) * OUTC + oc0 + o];
            sWh[(t * 64 + o) * 18 + cl] = (u16)(v & 0xffffu);
        }
        // X halo: both planes (A operand must be exact)
        for (int i = tid; i < 2880; i += 256) {
            int col = i % 18;
            int row = (i / 18) % 10;
            int cl  = i / 180;
            int gr = r0 - 1 + row, gc = c0x - 1 + col;
            u32 v = 0;
            if ((unsigned)gr < 128u && (unsigned)gc < 128u)
                v = g_enh2[(((size_t)b * CC + ch * 16 + cl) << 14) + (gr << 7) + gc];
            int si = (row * 18 + col) * 18 + cl;
            sXh[si] = (u16)(v & 0xffffu);
            sXl[si] = (u16)(v >> 16);
        }
        __syncthreads();

        #pragma unroll
        for (int t = 0; t < 9; t++) {
            const int dr = t / 3, dc = t % 3;
            u32 bh[4][2];
            #pragma unroll
            for (int qq = 0; qq < 4; qq++) {
                int widx = (t * 64 + (q0 + qq) * 8 + g) * 18 + t2;
                bh[qq][0] = *(const u32*)(sWh + widx);
                bh[qq][1] = *(const u32*)(sWh + widx + 8);
            }
            #pragma unroll
            for (int ff = 0; ff < 2; ff++) {
                int f = f0 + ff;
                int p0i = ((f + dr) * 18 + g + dc) * 18 + t2;
                int p1i = ((f + dr) * 18 + g + 8 + dc) * 18 + t2;
                u32 ah0 = *(const u32*)(sXh + p0i);
                u32 ah1 = *(const u32*)(sXh + p1i);
                u32 ah2 = *(const u32*)(sXh + p0i + 8);
                u32 ah3 = *(const u32*)(sXh + p1i + 8);
                u32 al0 = *(const u32*)(sXl + p0i);
                u32 al1 = *(const u32*)(sXl + p1i);
                u32 al2 = *(const u32*)(sXl + p0i + 8);
                u32 al3 = *(const u32*)(sXl + p1i + 8);
                #pragma unroll
                for (int qq = 0; qq < 4; qq++) {
                    mma_f16(acc[ff][qq], ah0, ah1, ah2, ah3, bh[qq][0], bh[qq][1]);
                    mma_f16(acc[ff][qq], al0, al1, al2, al3, bh[qq][0], bh[qq][1]);
                }
            }
        }
        __syncthreads();
    }

    #pragma unroll
    for (int ff = 0; ff < 2; ff++) {
        int orow = r0 + f0 + ff;
        #pragma unroll
        for (int qq = 0; qq < 4; qq++) {
            int oca = oc0 + (q0 + qq) * 8 + t2;
            float ba = g_dynb[b * OUTC + oca];
            float bb = g_dynb[b * OUTC + oca + 1];
            size_t basea = ((size_t)(b * OUTC + oca) * HH + orow) * WW + c0x + g;
            size_t baseb = ((size_t)(b * OUTC + oca + 1) * HH + orow) * WW + c0x + g;
            out[basea]     = acc[ff][qq][0] + ba;
            out[baseb]     = acc[ff][qq][1] + bb;
            out[basea + 8] = acc[ff][qq][2] + ba;
            out[baseb + 8] = acc[ff][qq][3] + bb;
        }
    }
}

// ============================================================
extern "C" void kernel_launch(void* const* d_in, const int* in_sizes, int n_in,
                              void* d_out, int out_size) {
    const float* ir    = (const float*)d_in[0];
    const float* vi    = (const float*)d_in[1];
    const float* kg_w1 = (const float*)d_in[2];
    const float* kg_b1 = (const float*)d_in[3];
    const float* kg_w2 = (const float*)d_in[4];
    const float* kg_b2 = (const float*)d_in[5];
    const float* bg_w1 = (const float*)d_in[6];
    const float* bg_b1 = (const float*)d_in[7];
    const float* bg_w2 = (const float*)d_in[8];
    const float* bg_b2 = (const float*)d_in[9];
    const float* en_w  = (const float*)d_in[10];
    const float* gmma  = (const float*)d_in[11];
    const float* beta  = (const float*)d_in[12];
    const float* mean  = (const float*)d_in[13];
    const float* var   = (const float*)d_in[14];
    float* out = (float*)d_out;

    static int smem_set = 0;
    if (!smem_set) {
        cudaFuncSetAttribute(dconv_mma_kernel,
                             cudaFuncAttributeMaxDynamicSharedMemorySize, DSM_BYTES);
        smem_set = 1;
    }

    pool_kernel<<<BB * C2, 256>>>(ir, vi);
    mlp1_kernel<<<BB, 128>>>(kg_w1, kg_b1, bg_w1, bg_b1);
    dynk_kernel<<<WKTOT / 256, 256>>>(kg_w2, kg_b2);
    dynb_kernel<<<BB, OUTC>>>(bg_w2, bg_b2);
    ewsplit_kernel<<<OUTC * C2 / 256, 256>>>(en_w);
    enh_mma_kernel<<<dim3(HW / 64, BB), 256>>>(ir, vi, gmma, beta, mean, var);
    dconv_mma_kernel<<<dim3(128, 2, BB), 256, DSM_BYTES>>>(out);
}

// round 11
// speedup vs baseline: 2.3738x; 1.4130x over previous
#include <cuda_runtime.h>
#include <cuda_fp16.h>

#define BB   16
#define CC   128
#define C2   256
#define OUTC 128
#define HH   128
#define WW   128
#define HW   16384
#define KGH  64
#define BGH  32
#define WKTOT   147456    /* OUT*C*9 */
#define CP   24           /* smem c-dim pad: conflict-free 48B stride */

typedef unsigned int u32;
typedef unsigned short u16;

// ---- scratch (device globals) ----
__device__ float g_pooled[BB * C2];
__device__ float g_hk[BB * KGH];
__device__ float g_hb[BB * BGH];
__device__ float g_dynb[BB * OUTC];
__device__ u32 g_ew2[OUTC * C2];                       // en_w fp16 split (hi|lo packed)
__device__ u16 g_enh_h[(size_t)BB * CC * HW];          // enhanced feature, fp16 (hi only)
__device__ u16 g_wkh[(size_t)BB * 9 * OUTC * CC];      // dyn weights fp16 [b][tap][o][c]

// fp16 two-term split: v = hi + lo (exact to ~2^-22)
__device__ __forceinline__ u32 pack_split(float v) {
    __half h = __float2half(v);
    u16 hu = __half_as_ushort(h);
    float rem = v - __half2float(h);
    u16 lu = __half_as_ushort(__float2half(rem));
    return ((u32)lu << 16) | hu;
}

__device__ __forceinline__ void mma_f16(float* d, u32 a0, u32 a1, u32 a2, u32 a3,
                                        u32 b0, u32 b1) {
    asm volatile(
        "mma.sync.aligned.m16n8k16.row.col.f32.f16.f16.f32 "
        "{%0,%1,%2,%3}, {%4,%5,%6,%7}, {%8,%9}, {%0,%1,%2,%3};"
        : "+f"(d[0]), "+f"(d[1]), "+f"(d[2]), "+f"(d[3])
        : "r"(a0), "r"(a1), "r"(a2), "r"(a3), "r"(b0), "r"(b1));
}

// ============================================================
// 1) global average pool of concat([ir, vi])
// ============================================================
__global__ void pool_kernel(const float* __restrict__ ir, const float* __restrict__ vi) {
    int bc = blockIdx.x;
    int b  = bc >> 8;
    int ch = bc & 255;
    const float* src = (ch < CC) ? ir + (size_t)(b * CC + ch) * HW
                                 : vi + (size_t)(b * CC + (ch - CC)) * HW;
    const float4* s4 = (const float4*)src;
    float sum = 0.f;
    for (int i = threadIdx.x; i < HW / 4; i += 256) {
        float4 v = s4[i];
        sum += v.x + v.y + v.z + v.w;
    }
    __shared__ float red[8];
    #pragma unroll
    for (int o = 16; o > 0; o >>= 1) sum += __shfl_down_sync(0xffffffffu, sum, o);
    if ((threadIdx.x & 31) == 0) red[threadIdx.x >> 5] = sum;
    __syncthreads();
    if (threadIdx.x == 0) {
        float t = 0.f;
        #pragma unroll
        for (int i = 0; i < 8; i++) t += red[i];
        g_pooled[b * C2 + ch] = t * (1.0f / HW);
    }
}

// ============================================================
// 2) hidden MLP layers
// ============================================================
__global__ void mlp1_kernel(const float* __restrict__ kg_w1, const float* __restrict__ kg_b1,
                            const float* __restrict__ bg_w1, const float* __restrict__ bg_b1) {
    int b = blockIdx.x;
    __shared__ float p[C2];
    for (int i = threadIdx.x; i < C2; i += 128) p[i] = g_pooled[b * C2 + i];
    __syncthreads();
    int t = threadIdx.x;
    if (t < KGH) {
        float acc = kg_b1[t];
        const float* w = kg_w1 + t * C2;
        for (int k = 0; k < C2; k++) acc = fmaf(p[k], w[k], acc);
        g_hk[b * KGH + t] = fmaxf(acc, 0.f);
    } else if (t < KGH + BGH) {
        int u = t - KGH;
        float acc = bg_b1[u];
        const float* w = bg_w1 + u * C2;
        for (int k = 0; k < C2; k++) acc = fmaf(p[k], w[k], acc);
        g_hb[b * BGH + u] = fmaxf(acc, 0.f);
    }
}

// ============================================================
// 3) dyn_k = hk @ kg_w2^T + kg_b2, fp16 -> g_wkh [b][t][o][c]
// ============================================================
__global__ void dynk_kernel(const float* __restrict__ kg_w2, const float* __restrict__ kg_b2) {
    int j = blockIdx.x * 256 + threadIdx.x;     // j = o*1152 + c*9 + t
    __shared__ float hk_s[BB * KGH];
    for (int i = threadIdx.x; i < BB * KGH; i += 256) hk_s[i] = g_hk[i];
    __syncthreads();
    float bias = kg_b2[j];
    float acc[BB];
    #pragma unroll
    for (int b = 0; b < BB; b++) acc[b] = bias;
    const float4* w4 = (const float4*)(kg_w2 + (size_t)j * KGH);
    for (int kk = 0; kk < KGH / 4; kk++) {
        float4 w = w4[kk];
        #pragma unroll
        for (int b = 0; b < BB; b++) {
            const float* h = hk_s + b * KGH + kk * 4;
            acc[b] += w.x * h[0] + w.y * h[1] + w.z * h[2] + w.w * h[3];
        }
    }
    int t = j % 9;
    int c = (j / 9) & 127;
    int o = j / 1152;
    #pragma unroll
    for (int b = 0; b < BB; b++)
        g_wkh[(((size_t)b * 9 + t) * OUTC + o) * CC + c] =
            __half_as_ushort(__float2half(acc[b]));
}

// ============================================================
// 4) dyn_b
// ============================================================
__global__ void dynb_kernel(const float* __restrict__ bg_w2, const float* __restrict__ bg_b2) {
    int b = blockIdx.x, o = threadIdx.x;
    float acc = bg_b2[o];
    const float* w = bg_w2 + o * BGH;
    const float* h = g_hb + b * BGH;
    for (int k = 0; k < BGH; k++) acc = fmaf(w[k], h[k], acc);
    g_dynb[b * OUTC + o] = acc;
}

// ============================================================
// 4b) one-shot fp16 split of en_w
// ============================================================
__global__ void ewsplit_kernel(const float* __restrict__ en_w) {
    int i = blockIdx.x * 256 + threadIdx.x;     // 32768 elems
    g_ew2[i] = pack_split(en_w[i]);
}

// ============================================================
// 5) enhance GEMM (fp16 2-product: W split exact, X rounded) + BN + ReLU
//    output stored as fp16 hi plane only
// ============================================================
__global__ __launch_bounds__(256) void enh_mma_kernel(
    const float* __restrict__ ir, const float* __restrict__ vi,
    const float* __restrict__ gmma, const float* __restrict__ beta,
    const float* __restrict__ mean, const float* __restrict__ var) {
    __shared__ u16 sWh[128 * CP];
    __shared__ u16 sWl[128 * CP];
    __shared__ u16 sXh[64 * CP];

    int b  = blockIdx.y;
    int p0 = blockIdx.x * 64;
    int tid  = threadIdx.x;
    int w    = tid >> 5;
    int lane = tid & 31;
    int g    = lane >> 2;
    int t2   = (lane & 3) * 2;

    float acc[8][4];
    #pragma unroll
    for (int i = 0; i < 8; i++)
        #pragma unroll
        for (int j = 0; j < 4; j++) acc[i][j] = 0.f;

    for (int k0 = 0; k0 < C2; k0 += 16) {
        #pragma unroll
        for (int r = 0; r < 8; r++) {
            int i = tid + r * 256;
            int oc = i >> 4, kk = i & 15;
            u32 v = g_ew2[oc * C2 + k0 + kk];
            sWh[oc * CP + kk] = (u16)(v & 0xffffu);
            sWl[oc * CP + kk] = (u16)(v >> 16);
        }
        #pragma unroll
        for (int r = 0; r < 4; r++) {
            int i = tid + r * 256;
            int cl = i >> 6, px = i & 63;
            int k = k0 + cl;
            const float* src = (k < CC) ? ir + (size_t)(b * CC + k) * HW
                                        : vi + (size_t)(b * CC + k - CC) * HW;
            sXh[px * CP + cl] = __half_as_ushort(__float2half(src[p0 + px]));
        }
        __syncthreads();

        int arow0 = (w * 16 + g) * CP;
        int arow1 = (w * 16 + g + 8) * CP;
        u32 ah0 = *(const u32*)(sWh + arow0 + t2);
        u32 ah1 = *(const u32*)(sWh + arow1 + t2);
        u32 ah2 = *(const u32*)(sWh + arow0 + t2 + 8);
        u32 ah3 = *(const u32*)(sWh + arow1 + t2 + 8);
        u32 al0 = *(const u32*)(sWl + arow0 + t2);
        u32 al1 = *(const u32*)(sWl + arow1 + t2);
        u32 al2 = *(const u32*)(sWl + arow0 + t2 + 8);
        u32 al3 = *(const u32*)(sWl + arow1 + t2 + 8);

        #pragma unroll
        for (int nf = 0; nf < 8; nf++) {
            int bidx = (nf * 8 + g) * CP + t2;
            u32 bh0 = *(const u32*)(sXh + bidx);
            u32 bh1 = *(const u32*)(sXh + bidx + 8);
            mma_f16(acc[nf], ah0, ah1, ah2, ah3, bh0, bh1);
            mma_f16(acc[nf], al0, al1, al2, al3, bh0, bh1);
        }
        __syncthreads();
    }

    int oc0 = w * 16 + g;
    int oc1 = oc0 + 8;
    float inv0 = gmma[oc0] * rsqrtf(var[oc0] + 1e-5f);
    float sh0  = beta[oc0] - mean[oc0] * inv0;
    float inv1 = gmma[oc1] * rsqrtf(var[oc1] + 1e-5f);
    float sh1  = beta[oc1] - mean[oc1] * inv1;
    #pragma unroll
    for (int nf = 0; nf < 8; nf++) {
        int px = p0 + nf * 8 + t2;   // even -> u32-aligned in u16 array
        u16 a0 = __half_as_ushort(__float2half(fmaxf(fmaf(acc[nf][0], inv0, sh0), 0.f)));
        u16 a1 = __half_as_ushort(__float2half(fmaxf(fmaf(acc[nf][1], inv0, sh0), 0.f)));
        u16 b0 = __half_as_ushort(__float2half(fmaxf(fmaf(acc[nf][2], inv1, sh1), 0.f)));
        u16 b1 = __half_as_ushort(__float2half(fmaxf(fmaf(acc[nf][3], inv1, sh1), 0.f)));
        *(u32*)&g_enh_h[(size_t)(b * CC + oc0) * HW + px] = ((u32)a1 << 16) | a0;
        *(u32*)&g_enh_h[(size_t)(b * CC + oc1) * HW + px] = ((u32)b1 << 16) | b0;
    }
}

// ============================================================
// 6) dynamic conv: 9 tap-GEMMs, fp16 SINGLE product (X and W both fp16)
//    8x16 px tile; conflict-free smem (pad CP=24)
// ============================================================
__global__ __launch_bounds__(256) void dconv_mma_kernel(float* __restrict__ out) {
    __shared__ u16 sWh[9 * 64 * CP];     // [tap][o][c16 pad]
    __shared__ u16 sX[10 * 18 * CP];     // [row][col][c16 pad]

    int b    = blockIdx.z;
    int oc0  = blockIdx.y * 64;
    int tile = blockIdx.x;                 // 16 row-bands x 8 col-tiles
    int r0  = (tile >> 3) * 8;
    int c0x = (tile & 7) * 16;

    int tid  = threadIdx.x;
    int w    = tid >> 5;
    int lane = tid & 31;
    int g    = lane >> 2;
    int t2   = (lane & 3) * 2;
    int f0   = (w & 3) * 2;
    int q0   = (w >> 2) * 4;

    float acc[2][4][4];
    #pragma unroll
    for (int i = 0; i < 2; i++)
        #pragma unroll
        for (int j = 0; j < 4; j++)
            #pragma unroll
            for (int k = 0; k < 4; k++) acc[i][j][k] = 0.f;

    for (int ch = 0; ch < 8; ch++) {
        // W fill: u32 loads (2 c-values, c-contiguous gmem), conflict-free STS.32
        // 4608 u32 total: icl = u32-in-row, o, t
        for (int i = tid; i < 4608; i += 256) {
            int icl = i & 7;
            int o   = (i >> 3) & 63;
            int t   = i >> 9;
            u32 v = *(const u32*)(g_wkh +
                    (((size_t)b * 9 + t) * OUTC + oc0 + o) * CC + ch * 16 + icl * 2);
            *(u32*)(sWh + (t * 64 + o) * CP + icl * 2) = v;
        }
        // X halo fill: single fp16 plane, u16 loads
        for (int i = tid; i < 2880; i += 256) {
            int col = i % 18;
            int row = (i / 18) % 10;
            int cl  = i / 180;
            int gr = r0 - 1 + row, gc = c0x - 1 + col;
            u16 v = 0;
            if ((unsigned)gr < 128u && (unsigned)gc < 128u)
                v = g_enh_h[(((size_t)b * CC + ch * 16 + cl) << 14) + (gr << 7) + gc];
            sX[(row * 18 + col) * CP + cl] = v;
        }
        __syncthreads();

        #pragma unroll
        for (int t = 0; t < 9; t++) {
            const int dr = t / 3, dc = t % 3;
            u32 bh[4][2];
            #pragma unroll
            for (int qq = 0; qq < 4; qq++) {
                int widx = (t * 64 + (q0 + qq) * 8 + g) * CP + t2;
                bh[qq][0] = *(const u32*)(sWh + widx);
                bh[qq][1] = *(const u32*)(sWh + widx + 8);
            }
            #pragma unroll
            for (int ff = 0; ff < 2; ff++) {
                int f = f0 + ff;
                int p0i = ((f + dr) * 18 + g + dc) * CP + t2;
                int p1i = ((f + dr) * 18 + g + 8 + dc) * CP + t2;
                u32 ah0 = *(const u32*)(sX + p0i);
                u32 ah1 = *(const u32*)(sX + p1i);
                u32 ah2 = *(const u32*)(sX + p0i + 8);
                u32 ah3 = *(const u32*)(sX + p1i + 8);
                #pragma unroll
                for (int qq = 0; qq < 4; qq++)
                    mma_f16(acc[ff][qq], ah0, ah1, ah2, ah3, bh[qq][0], bh[qq][1]);
            }
        }
        __syncthreads();
    }

    #pragma unroll
    for (int ff = 0; ff < 2; ff++) {
        int orow = r0 + f0 + ff;
        #pragma unroll
        for (int qq = 0; qq < 4; qq++) {
            int oca = oc0 + (q0 + qq) * 8 + t2;
            float ba = g_dynb[b * OUTC + oca];
            float bb = g_dynb[b * OUTC + oca + 1];
            size_t basea = ((size_t)(b * OUTC + oca) * HH + orow) * WW + c0x + g;
            size_t baseb = ((size_t)(b * OUTC + oca + 1) * HH + orow) * WW + c0x + g;
            out[basea]     = acc[ff][qq][0] + ba;
            out[baseb]     = acc[ff][qq][1] + bb;
            out[basea + 8] = acc[ff][qq][2] + ba;
            out[baseb + 8] = acc[ff][qq][3] + bb;
        }
    }
}

// ============================================================
extern "C" void kernel_launch(void* const* d_in, const int* in_sizes, int n_in,
                              void* d_out, int out_size) {
    const float* ir    = (const float*)d_in[0];
    const float* vi    = (const float*)d_in[1];
    const float* kg_w1 = (const float*)d_in[2];
    const float* kg_b1 = (const float*)d_in[3];
    const float* kg_w2 = (const float*)d_in[4];
    const float* kg_b2 = (const float*)d_in[5];
    const float* bg_w1 = (const float*)d_in[6];
    const float* bg_b1 = (const float*)d_in[7];
    const float* bg_w2 = (const float*)d_in[8];
    const float* bg_b2 = (const float*)d_in[9];
    const float* en_w  = (const float*)d_in[10];
    const float* gmma  = (const float*)d_in[11];
    const float* beta  = (const float*)d_in[12];
    const float* mean  = (const float*)d_in[13];
    const float* var   = (const float*)d_in[14];
    float* out = (float*)d_out;

    pool_kernel<<<BB * C2, 256>>>(ir, vi);
    mlp1_kernel<<<BB, 128>>>(kg_w1, kg_b1, bg_w1, bg_b1);
    dynk_kernel<<<WKTOT / 256, 256>>>(kg_w2, kg_b2);
    dynb_kernel<<<BB, OUTC>>>(bg_w2, bg_b2);
    ewsplit_kernel<<<OUTC * C2 / 256, 256>>>(en_w);
    enh_mma_kernel<<<dim3(HW / 64, BB), 256>>>(ir, vi, gmma, beta, mean, var);
    dconv_mma_kernel<<<dim3(128, 2, BB), 256>>>(out);
}